// round 1
// baseline (speedup 1.0000x reference)
#include <cuda_runtime.h>
#include <math.h>

#define NG 1024
#define IMG_H 128
#define IMG_W 128
#define FX 128.0f
#define FY 128.0f
#define CLIPX 0.65f   // 1.3 * TANX
#define CLIPY 0.65f   // 1.3 * TANY

// ---------------- device scratch (no allocations allowed) ----------------
__device__ float g_key[NG];
__device__ float g_x[NG], g_y[NG], g_A[NG], g_B[NG], g_C[NG];
__device__ float g_op[NG], g_pth[NG], g_r[NG], g_g[NG], g_b[NG];
__device__ float4 s_geo[NG];   // x, y, conA, conB   (sorted)
__device__ float4 s_col[NG];   // conC, r, g, b      (sorted)
__device__ float2 s_opc[NG];   // opacity, pthresh   (sorted)
__device__ int    g_nvalid;

// ---------------- K1: per-gaussian preprocess ----------------
__global__ __launch_bounds__(256)
void preprocess_kernel(const float* __restrict__ means3D,
                       const float* __restrict__ opacities,
                       const float* __restrict__ shs,
                       const float* __restrict__ scales,
                       const float* __restrict__ rotations,
                       const float* __restrict__ vm,   // viewmatrix 4x4 row-major
                       const float* __restrict__ pm,   // projmatrix 4x4 row-major
                       const float* __restrict__ campos,
                       float* __restrict__ out)        // radii written at out[49152+i]
{
    int i = blockIdx.x * blockDim.x + threadIdx.x;
    if (i >= NG) return;

    float mx = means3D[3*i+0], my = means3D[3*i+1], mz = means3D[3*i+2];

    // p_view = hom @ viewmatrix
    float pv0 = mx*vm[0] + my*vm[4] + mz*vm[8]  + vm[12];
    float pv1 = mx*vm[1] + my*vm[5] + mz*vm[9]  + vm[13];
    float pv2 = mx*vm[2] + my*vm[6] + mz*vm[10] + vm[14];
    float depth = pv2;

    // p_hom = hom @ projmatrix
    float ph0 = mx*pm[0] + my*pm[4] + mz*pm[8]  + pm[12];
    float ph1 = mx*pm[1] + my*pm[5] + mz*pm[9]  + pm[13];
    float ph3 = mx*pm[3] + my*pm[7] + mz*pm[11] + pm[15];
    float invw = 1.0f / (ph3 + 1e-7f);
    float ppx = ph0 * invw, ppy = ph1 * invw;

    // quaternion -> rotation
    float qr = rotations[4*i+0], qx = rotations[4*i+1];
    float qy = rotations[4*i+2], qz = rotations[4*i+3];
    float qn = rsqrtf(qr*qr + qx*qx + qy*qy + qz*qz);
    qr *= qn; qx *= qn; qy *= qn; qz *= qn;
    float R00 = 1.f - 2.f*(qy*qy + qz*qz), R01 = 2.f*(qx*qy - qr*qz), R02 = 2.f*(qx*qz + qr*qy);
    float R10 = 2.f*(qx*qy + qr*qz), R11 = 1.f - 2.f*(qx*qx + qz*qz), R12 = 2.f*(qy*qz - qr*qx);
    float R20 = 2.f*(qx*qz - qr*qy), R21 = 2.f*(qy*qz + qr*qx), R22 = 1.f - 2.f*(qx*qx + qy*qy);

    float s0 = scales[3*i+0], s1 = scales[3*i+1], s2 = scales[3*i+2];
    float M00 = R00*s0, M01 = R01*s1, M02 = R02*s2;
    float M10 = R10*s0, M11 = R11*s1, M12 = R12*s2;
    float M20 = R20*s0, M21 = R21*s1, M22 = R22*s2;

    // Sigma = M M^T (symmetric)
    float S00 = M00*M00 + M01*M01 + M02*M02;
    float S01 = M00*M10 + M01*M11 + M02*M12;
    float S02 = M00*M20 + M01*M21 + M02*M22;
    float S11 = M10*M10 + M11*M11 + M12*M12;
    float S12 = M10*M20 + M11*M21 + M12*M22;
    float S22 = M20*M20 + M21*M21 + M22*M22;

    float tz = (depth > 0.2f) ? depth : 1.0f;
    float invz = 1.0f / tz;
    float txtz = fminf(fmaxf(pv0*invz, -CLIPX), CLIPX) * tz;
    float tytz = fminf(fmaxf(pv1*invz, -CLIPY), CLIPY) * tz;
    float J00 = FX*invz, J02 = -FX*txtz*invz*invz;
    float J11 = FY*invz, J12 = -FY*tytz*invz*invz;

    // T2 = J @ viewmatrix[:3,:3].T ;  Wr[j][k] = vm[4k+j]
    float t00 = J00*vm[0]  + J02*vm[2];
    float t01 = J00*vm[4]  + J02*vm[6];
    float t02 = J00*vm[8]  + J02*vm[10];
    float t10 = J11*vm[1]  + J12*vm[2];
    float t11 = J11*vm[5]  + J12*vm[6];
    float t12 = J11*vm[9]  + J12*vm[10];

    // cov2 = T2 Sigma T2^T
    float a = t00*t00*S00 + t01*t01*S11 + t02*t02*S22
            + 2.f*(t00*t01*S01 + t00*t02*S02 + t01*t02*S12) + 0.3f;
    float c = t10*t10*S00 + t11*t11*S11 + t12*t12*S22
            + 2.f*(t10*t11*S01 + t10*t12*S02 + t11*t12*S12) + 0.3f;
    float b = t00*t10*S00 + t01*t11*S11 + t02*t12*S22
            + (t00*t11 + t01*t10)*S01 + (t00*t12 + t02*t10)*S02 + (t01*t12 + t02*t11)*S12;

    float det = a*c - b*b;
    bool valid = (depth > 0.2f) && (det > 0.0f);
    float inv_det = 1.0f / ((det > 0.0f) ? det : 1.0f);
    float conA = c*inv_det, conB = -b*inv_det, conC = a*inv_det;

    float mid = 0.5f*(a + c);
    float lam1 = mid + sqrtf(fmaxf(0.1f, mid*mid - det));
    float radii = valid ? ceilf(3.0f * sqrtf(lam1)) : 0.0f;

    float xyx = ((ppx + 1.0f)*(float)IMG_W - 1.0f)*0.5f;
    float xyy = ((ppy + 1.0f)*(float)IMG_H - 1.0f)*0.5f;

    // view direction for SH
    float dx = mx - campos[0], dy = my - campos[1], dz = mz - campos[2];
    float dn = rsqrtf(dx*dx + dy*dy + dz*dz);
    float x = dx*dn, y = dy*dn, z = dz*dn;
    float xx = x*x, yy = y*y, zz = z*z;
    float xy = x*y, yz = y*z, xz = x*z;

    const float C0f = 0.28209479177387814f;
    const float C1f = 0.4886025119029199f;
    float basis[16];
    basis[0]  = C0f;
    basis[1]  = -C1f*y;
    basis[2]  =  C1f*z;
    basis[3]  = -C1f*x;
    basis[4]  =  1.0925484305920792f * xy;
    basis[5]  = -1.0925484305920792f * yz;
    basis[6]  =  0.31539156525252005f * (2.f*zz - xx - yy);
    basis[7]  = -1.0925484305920792f * xz;
    basis[8]  =  0.5462742152960396f * (xx - yy);
    basis[9]  = -0.5900435899266435f * y * (3.f*xx - yy);
    basis[10] =  2.890611442640554f  * xy * z;
    basis[11] = -0.4570457994644658f * y * (4.f*zz - xx - yy);
    basis[12] =  0.3731763325901154f * z * (2.f*zz - 3.f*xx - 3.f*yy);
    basis[13] = -0.4570457994644658f * x * (4.f*zz - xx - yy);
    basis[14] =  1.445305721320277f  * z * (xx - yy);
    basis[15] = -0.5900435899266435f * x * (xx - 3.f*yy);

    const float* sh = shs + i*48;
    float cr = 0.f, cg = 0.f, cb = 0.f;
    #pragma unroll
    for (int k = 0; k < 16; k++) {
        cr += basis[k]*sh[3*k+0];
        cg += basis[k]*sh[3*k+1];
        cb += basis[k]*sh[3*k+2];
    }
    cr = fmaxf(cr + 0.5f, 0.f);
    cg = fmaxf(cg + 0.5f, 0.f);
    cb = fmaxf(cb + 0.5f, 0.f);

    float op = opacities[i];

    g_key[i] = valid ? depth : INFINITY;
    g_x[i] = xyx;  g_y[i] = xyy;
    g_A[i] = conA; g_B[i] = conB; g_C[i] = conC;
    g_op[i] = op;
    g_pth[i] = -logf(255.0f * op);   // alpha>=1/255  <=>  power >= pth (given power<=0)
    g_r[i] = cr; g_g[i] = cg; g_b[i] = cb;

    out[IMG_H*IMG_W*3 + i] = radii;  // radii as float (output concatenation)
}

// ---------------- K2: bitonic sort by depth + gather ----------------
__global__ __launch_bounds__(1024)
void sort_kernel()
{
    __shared__ float k[NG];
    __shared__ int   v[NG];
    int t = threadIdx.x;
    k[t] = g_key[t];
    v[t] = t;
    __syncthreads();

    for (int size = 2; size <= NG; size <<= 1) {
        for (int stride = size >> 1; stride > 0; stride >>= 1) {
            int j = t ^ stride;
            if (j > t) {
                bool asc = ((t & size) == 0);
                float kt = k[t], kj = k[j];
                if ((kt > kj) == asc) {
                    k[t] = kj; k[j] = kt;
                    int vt = v[t]; v[t] = v[j]; v[j] = vt;
                }
            }
            __syncthreads();
        }
    }

    // number of valid (finite-key) gaussians — sorted, so find the boundary
    bool fin = isfinite(k[t]);
    if (fin && (t == NG-1 || !isfinite(k[t+1]))) g_nvalid = t + 1;
    if (t == 0 && !fin) g_nvalid = 0;

    int src = v[t];
    s_geo[t] = make_float4(g_x[src], g_y[src], g_A[src], g_B[src]);
    s_col[t] = make_float4(g_C[src], g_r[src], g_g[src], g_b[src]);
    s_opc[t] = make_float2(g_op[src], g_pth[src]);
}

// ---------------- K3: tiled front-to-back composite ----------------
__global__ __launch_bounds__(256)
void raster_kernel(const float* __restrict__ bg, float* __restrict__ out)
{
    __shared__ float4 shg[256];
    __shared__ float4 shc[256];
    __shared__ float2 sho[256];

    int tx = threadIdx.x, ty = threadIdx.y;
    int px = blockIdx.x*16 + tx;
    int py = blockIdx.y*16 + ty;
    float fx = (float)px, fy = (float)py;
    int tid = ty*16 + tx;

    float T = 1.0f;          // running transmittance (== Tae until termination)
    float cr = 0.f, cg = 0.f, cb = 0.f;
    bool done = false;
    int nv = g_nvalid;

    for (int base = 0; base < nv; base += 256) {
        int i = base + tid;
        if (i < nv) {
            shg[tid] = s_geo[i];
            shc[tid] = s_col[i];
            sho[tid] = s_opc[i];
        }
        __syncthreads();

        int cnt = min(256, nv - base);
        if (!done) {
            for (int j = 0; j < cnt; j++) {
                float4 ge = shg[j];
                float dx = ge.x - fx;
                float dy = ge.y - fy;
                float conC = shc[j].x;
                float power = -0.5f*(ge.z*dx*dx + conC*dy*dy) - ge.w*dx*dy;
                float2 op = sho[j];
                if (power > 0.0f || power < op.y) continue;   // alpha would be < 1/255
                float alpha = fminf(0.99f, op.x * expf(power));
                if (alpha < (1.0f/255.0f)) continue;
                float Tnew = T * (1.0f - alpha);
                if (Tnew < 1e-4f) { done = true; break; }     // ae=0 from here on, T frozen
                float w = T * alpha;
                float4 col = shc[j];
                cr += w * col.y;
                cg += w * col.z;
                cb += w * col.w;
                T = Tnew;
            }
        }
        if (__syncthreads_count(done ? 1 : 0) == 256) break;
    }

    int pix = py*IMG_W + px;
    out[0*IMG_H*IMG_W + pix] = cr + bg[0]*T;
    out[1*IMG_H*IMG_W + pix] = cg + bg[1]*T;
    out[2*IMG_H*IMG_W + pix] = cb + bg[2]*T;
}

// ---------------- launch ----------------
extern "C" void kernel_launch(void* const* d_in, const int* in_sizes, int n_in,
                              void* d_out, int out_size)
{
    const float* means3D   = (const float*)d_in[0];
    // d_in[1] = means2D (unused)
    const float* opacities = (const float*)d_in[2];
    const float* shs       = (const float*)d_in[3];
    const float* scales    = (const float*)d_in[4];
    const float* rotations = (const float*)d_in[5];
    const float* viewm     = (const float*)d_in[6];
    const float* projm     = (const float*)d_in[7];
    const float* campos    = (const float*)d_in[8];
    const float* bg        = (const float*)d_in[9];
    float* out = (float*)d_out;

    preprocess_kernel<<<NG/256, 256>>>(means3D, opacities, shs, scales, rotations,
                                       viewm, projm, campos, out);
    sort_kernel<<<1, NG>>>();
    raster_kernel<<<dim3(IMG_W/16, IMG_H/16), dim3(16,16)>>>(bg, out);
}

// round 2
// speedup vs baseline: 2.8760x; 2.8760x over previous
#include <cuda_runtime.h>
#include <math.h>

#define NG 1024
#define IMG_H 128
#define IMG_W 128
#define FX 128.0f
#define FY 128.0f
#define CLIPX 0.65f   // 1.3 * TANX
#define CLIPY 0.65f   // 1.3 * TANY

// ---------------- device scratch (no allocations allowed) ----------------
__device__ float g_key[NG];
__device__ float g_x[NG], g_y[NG], g_A[NG], g_B[NG], g_C[NG];
__device__ float g_op[NG], g_pth[NG], g_rx[NG], g_ry[NG];
__device__ float g_r[NG], g_g[NG], g_b[NG];
__device__ float4 s_geo[NG];   // x, y, conA, conB      (sorted by depth)
__device__ float4 s_col[NG];   // conC, r, g, b         (sorted)
__device__ float4 s_opc[NG];   // opacity, pth, rx, ry  (sorted)
__device__ int    g_nvalid;

// ---------------- K1: per-gaussian preprocess ----------------
__global__ __launch_bounds__(256)
void preprocess_kernel(const float* __restrict__ means3D,
                       const float* __restrict__ opacities,
                       const float* __restrict__ shs,
                       const float* __restrict__ scales,
                       const float* __restrict__ rotations,
                       const float* __restrict__ vm,   // viewmatrix 4x4 row-major
                       const float* __restrict__ pm,   // projmatrix 4x4 row-major
                       const float* __restrict__ campos,
                       float* __restrict__ out)        // radii written at out[49152+i]
{
    int i = blockIdx.x * blockDim.x + threadIdx.x;
    if (i >= NG) return;

    float mx = means3D[3*i+0], my = means3D[3*i+1], mz = means3D[3*i+2];

    // p_view = hom @ viewmatrix
    float pv0 = mx*vm[0] + my*vm[4] + mz*vm[8]  + vm[12];
    float pv1 = mx*vm[1] + my*vm[5] + mz*vm[9]  + vm[13];
    float pv2 = mx*vm[2] + my*vm[6] + mz*vm[10] + vm[14];
    float depth = pv2;

    // p_hom = hom @ projmatrix
    float ph0 = mx*pm[0] + my*pm[4] + mz*pm[8]  + pm[12];
    float ph1 = mx*pm[1] + my*pm[5] + mz*pm[9]  + pm[13];
    float ph3 = mx*pm[3] + my*pm[7] + mz*pm[11] + pm[15];
    float invw = 1.0f / (ph3 + 1e-7f);
    float ppx = ph0 * invw, ppy = ph1 * invw;

    // quaternion -> rotation (vectorized load)
    float4 q = reinterpret_cast<const float4*>(rotations)[i];
    float qr = q.x, qx = q.y, qy = q.z, qz = q.w;
    float qn = rsqrtf(qr*qr + qx*qx + qy*qy + qz*qz);
    qr *= qn; qx *= qn; qy *= qn; qz *= qn;
    float R00 = 1.f - 2.f*(qy*qy + qz*qz), R01 = 2.f*(qx*qy - qr*qz), R02 = 2.f*(qx*qz + qr*qy);
    float R10 = 2.f*(qx*qy + qr*qz), R11 = 1.f - 2.f*(qx*qx + qz*qz), R12 = 2.f*(qy*qz - qr*qx);
    float R20 = 2.f*(qx*qz - qr*qy), R21 = 2.f*(qy*qz + qr*qx), R22 = 1.f - 2.f*(qx*qx + qy*qy);

    float s0 = scales[3*i+0], s1 = scales[3*i+1], s2 = scales[3*i+2];
    float M00 = R00*s0, M01 = R01*s1, M02 = R02*s2;
    float M10 = R10*s0, M11 = R11*s1, M12 = R12*s2;
    float M20 = R20*s0, M21 = R21*s1, M22 = R22*s2;

    // Sigma = M M^T (symmetric)
    float S00 = M00*M00 + M01*M01 + M02*M02;
    float S01 = M00*M10 + M01*M11 + M02*M12;
    float S02 = M00*M20 + M01*M21 + M02*M22;
    float S11 = M10*M10 + M11*M11 + M12*M12;
    float S12 = M10*M20 + M11*M21 + M12*M22;
    float S22 = M20*M20 + M21*M21 + M22*M22;

    float tz = (depth > 0.2f) ? depth : 1.0f;
    float invz = 1.0f / tz;
    float txtz = fminf(fmaxf(pv0*invz, -CLIPX), CLIPX) * tz;
    float tytz = fminf(fmaxf(pv1*invz, -CLIPY), CLIPY) * tz;
    float J00 = FX*invz, J02 = -FX*txtz*invz*invz;
    float J11 = FY*invz, J12 = -FY*tytz*invz*invz;

    // T2 = J @ viewmatrix[:3,:3].T ;  Wr[j][k] = vm[4k+j]
    float t00 = J00*vm[0]  + J02*vm[2];
    float t01 = J00*vm[4]  + J02*vm[6];
    float t02 = J00*vm[8]  + J02*vm[10];
    float t10 = J11*vm[1]  + J12*vm[2];
    float t11 = J11*vm[5]  + J12*vm[6];
    float t12 = J11*vm[9]  + J12*vm[10];

    // cov2 = T2 Sigma T2^T
    float a = t00*t00*S00 + t01*t01*S11 + t02*t02*S22
            + 2.f*(t00*t01*S01 + t00*t02*S02 + t01*t02*S12) + 0.3f;
    float c = t10*t10*S00 + t11*t11*S11 + t12*t12*S22
            + 2.f*(t10*t11*S01 + t10*t12*S02 + t11*t12*S12) + 0.3f;
    float b = t00*t10*S00 + t01*t11*S11 + t02*t12*S22
            + (t00*t11 + t01*t10)*S01 + (t00*t12 + t02*t10)*S02 + (t01*t12 + t02*t11)*S12;

    float det = a*c - b*b;
    bool valid = (depth > 0.2f) && (det > 0.0f);
    float inv_det = 1.0f / ((det > 0.0f) ? det : 1.0f);
    float conA = c*inv_det, conB = -b*inv_det, conC = a*inv_det;

    float mid = 0.5f*(a + c);
    float lam1 = mid + sqrtf(fmaxf(0.1f, mid*mid - det));
    float radii = valid ? ceilf(3.0f * sqrtf(lam1)) : 0.0f;

    float xyx = ((ppx + 1.0f)*(float)IMG_W - 1.0f)*0.5f;
    float xyy = ((ppy + 1.0f)*(float)IMG_H - 1.0f)*0.5f;

    // view direction for SH
    float dx = mx - campos[0], dy = my - campos[1], dz = mz - campos[2];
    float dn = rsqrtf(dx*dx + dy*dy + dz*dz);
    float x = dx*dn, y = dy*dn, z = dz*dn;
    float xx = x*x, yy = y*y, zz = z*z;
    float xy = x*y, yz = y*z, xz = x*z;

    const float C0f = 0.28209479177387814f;
    const float C1f = 0.4886025119029199f;
    float basis[16];
    basis[0]  = C0f;
    basis[1]  = -C1f*y;
    basis[2]  =  C1f*z;
    basis[3]  = -C1f*x;
    basis[4]  =  1.0925484305920792f * xy;
    basis[5]  = -1.0925484305920792f * yz;
    basis[6]  =  0.31539156525252005f * (2.f*zz - xx - yy);
    basis[7]  = -1.0925484305920792f * xz;
    basis[8]  =  0.5462742152960396f * (xx - yy);
    basis[9]  = -0.5900435899266435f * y * (3.f*xx - yy);
    basis[10] =  2.890611442640554f  * xy * z;
    basis[11] = -0.4570457994644658f * y * (4.f*zz - xx - yy);
    basis[12] =  0.3731763325901154f * z * (2.f*zz - 3.f*xx - 3.f*yy);
    basis[13] = -0.4570457994644658f * x * (4.f*zz - xx - yy);
    basis[14] =  1.445305721320277f  * z * (xx - yy);
    basis[15] = -0.5900435899266435f * x * (xx - 3.f*yy);

    // vectorized SH load: 48 floats = 12 float4
    float shv[48];
    {
        const float4* sh4 = reinterpret_cast<const float4*>(shs + i*48);
        #pragma unroll
        for (int k = 0; k < 12; k++) {
            float4 v = sh4[k];
            shv[4*k+0] = v.x; shv[4*k+1] = v.y; shv[4*k+2] = v.z; shv[4*k+3] = v.w;
        }
    }
    float cr = 0.f, cg = 0.f, cb = 0.f;
    #pragma unroll
    for (int k = 0; k < 16; k++) {
        cr += basis[k]*shv[3*k+0];
        cg += basis[k]*shv[3*k+1];
        cb += basis[k]*shv[3*k+2];
    }
    cr = fmaxf(cr + 0.5f, 0.f);
    cg = fmaxf(cg + 0.5f, 0.f);
    cb = fmaxf(cb + 0.5f, 0.f);

    float op = opacities[i];
    float mpth = logf(255.0f * op);         // alpha>=1/255 <=> power >= -mpth (power<=0)

    // exact alpha-cutoff extents along screen axes:
    // level set {q(d) = 2*mpth} has extent sqrt(2*mpth*Sigma_xx) along x, etc.
    float rxe, rye;
    if (mpth > 0.0f) {
        rxe = sqrtf(2.0f*mpth*a);
        rye = sqrtf(2.0f*mpth*c);
    } else {
        rxe = -1.0f; rye = -1.0f;           // never reaches 1/255 even at center
    }

    g_key[i] = valid ? depth : INFINITY;
    g_x[i] = xyx;  g_y[i] = xyy;
    g_A[i] = conA; g_B[i] = conB; g_C[i] = conC;
    g_op[i] = op;
    g_pth[i] = -mpth;
    g_rx[i] = rxe; g_ry[i] = rye;
    g_r[i] = cr; g_g[i] = cg; g_b[i] = cb;

    out[IMG_H*IMG_W*3 + i] = radii;  // radii as float (output concatenation)
}

// ---------------- K2: bitonic sort by depth + gather ----------------
__global__ __launch_bounds__(1024)
void sort_kernel()
{
    __shared__ float k[NG];
    __shared__ int   v[NG];
    int t = threadIdx.x;
    k[t] = g_key[t];
    v[t] = t;
    __syncthreads();

    for (int size = 2; size <= NG; size <<= 1) {
        for (int stride = size >> 1; stride > 0; stride >>= 1) {
            int j = t ^ stride;
            if (j > t) {
                bool asc = ((t & size) == 0);
                float kt = k[t], kj = k[j];
                if ((kt > kj) == asc) {
                    k[t] = kj; k[j] = kt;
                    int vt = v[t]; v[t] = v[j]; v[j] = vt;
                }
            }
            __syncthreads();
        }
    }

    bool fin = isfinite(k[t]);
    if (fin && (t == NG-1 || !isfinite(k[t+1]))) g_nvalid = t + 1;
    if (t == 0 && !fin) g_nvalid = 0;

    int src = v[t];
    s_geo[t] = make_float4(g_x[src], g_y[src], g_A[src], g_B[src]);
    s_col[t] = make_float4(g_C[src], g_r[src], g_g[src], g_b[src]);
    s_opc[t] = make_float4(g_op[src], g_pth[src], g_rx[src], g_ry[src]);
}

// ---------------- K3: tiled composite with per-chunk block compaction ----------------
__global__ __launch_bounds__(256)
void raster_kernel(const float* __restrict__ bg, float* __restrict__ out)
{
    __shared__ float4 cgeo[256];
    __shared__ float4 ccol[256];
    __shared__ float2 copc[256];
    __shared__ int wcnt[8];
    __shared__ int woff[9];

    int tx = threadIdx.x, ty = threadIdx.y;
    int px = blockIdx.x*16 + tx;
    int py = blockIdx.y*16 + ty;
    float fx = (float)px, fy = (float)py;
    int tid = ty*16 + tx;
    int wid = tid >> 5, lane = tid & 31;

    float tminx = (float)(blockIdx.x*16);
    float tmaxx = tminx + 15.0f;
    float tminy = (float)(blockIdx.y*16);
    float tmaxy = tminy + 15.0f;

    float T = 1.0f;
    float cr = 0.f, cg = 0.f, cb = 0.f;
    bool done = false;
    int nv = g_nvalid;

    for (int base = 0; base < nv; base += 256) {
        int i = base + tid;

        // --- tile-vs-gaussian bbox cull (exact alpha>=1/255 extent) ---
        bool keep = false;
        float4 ge;
        float4 op;
        if (i < nv) {
            ge = s_geo[i];
            op = s_opc[i];
            float cx = fminf(fmaxf(ge.x, tminx), tmaxx);
            float cy = fminf(fmaxf(ge.y, tminy), tmaxy);
            keep = (fabsf(ge.x - cx) <= op.z) && (fabsf(ge.y - cy) <= op.w);
        }

        // --- order-preserving block compaction into shared ---
        unsigned m = __ballot_sync(0xffffffffu, keep);
        if (lane == 0) wcnt[wid] = __popc(m);
        __syncthreads();
        if (tid == 0) {
            int s = 0;
            #pragma unroll
            for (int w = 0; w < 8; w++) { woff[w] = s; s += wcnt[w]; }
            woff[8] = s;
        }
        __syncthreads();
        if (keep) {
            int pos = woff[wid] + __popc(m & ((1u << lane) - 1u));
            cgeo[pos] = ge;
            ccol[pos] = s_col[i];
            copc[pos] = make_float2(op.x, op.y);
        }
        __syncthreads();
        int cnt = woff[8];

        // --- per-pixel front-to-back composite over survivors ---
        if (!done) {
            for (int j = 0; j < cnt; j++) {
                float4 g4 = cgeo[j];
                float dx = g4.x - fx;
                float dy = g4.y - fy;
                float conC = ccol[j].x;
                float power = -0.5f*(g4.z*dx*dx + conC*dy*dy) - g4.w*dx*dy;
                float2 o2 = copc[j];
                if (power > 0.0f || power < o2.y) continue;
                float alpha = fminf(0.99f, o2.x * expf(power));
                if (alpha < (1.0f/255.0f)) continue;
                float Tnew = T * (1.0f - alpha);
                if (Tnew < 1e-4f) { done = true; break; }
                float w = T * alpha;
                float4 col = ccol[j];
                cr += w * col.y;
                cg += w * col.z;
                cb += w * col.w;
                T = Tnew;
            }
        }
        if (__syncthreads_count(done ? 1 : 0) == 256) break;
    }

    int pix = py*IMG_W + px;
    out[0*IMG_H*IMG_W + pix] = cr + bg[0]*T;
    out[1*IMG_H*IMG_W + pix] = cg + bg[1]*T;
    out[2*IMG_H*IMG_W + pix] = cb + bg[2]*T;
}

// ---------------- launch ----------------
extern "C" void kernel_launch(void* const* d_in, const int* in_sizes, int n_in,
                              void* d_out, int out_size)
{
    const float* means3D   = (const float*)d_in[0];
    // d_in[1] = means2D (unused)
    const float* opacities = (const float*)d_in[2];
    const float* shs       = (const float*)d_in[3];
    const float* scales    = (const float*)d_in[4];
    const float* rotations = (const float*)d_in[5];
    const float* viewm     = (const float*)d_in[6];
    const float* projm     = (const float*)d_in[7];
    const float* campos    = (const float*)d_in[8];
    const float* bg        = (const float*)d_in[9];
    float* out = (float*)d_out;

    preprocess_kernel<<<NG/256, 256>>>(means3D, opacities, shs, scales, rotations,
                                       viewm, projm, campos, out);
    sort_kernel<<<1, NG>>>();
    raster_kernel<<<dim3(IMG_W/16, IMG_H/16), dim3(16,16)>>>(bg, out);
}